// round 3
// baseline (speedup 1.0000x reference)
#include <cuda_runtime.h>
#include <cuda_bf16.h>

#define N_NODES 100000
#define N_EDGES 1600000
#define C_IN  64
#define C_HID 64
#define C_OUT 32

#define SCAN_B 256
#define N_SCAN_BLOCKS ((N_NODES + SCAN_B - 1) / SCAN_B)   // 391

// ---------------- scratch (device globals; no allocation allowed) ----------
__device__ int   g_src[N_EDGES];
__device__ int   g_dst[N_EDGES];
__device__ float g_deg[N_NODES];
__device__ float g_dinv[N_NODES];
__device__ int   g_cnt[N_NODES];    // in-degree (edge count)
__device__ int   g_fill[N_NODES];   // scatter cursor
__device__ int   g_row[N_NODES];    // exclusive scan of cnt
__device__ int   g_bsum[512];
__device__ int   g_boff[512];
__device__ int   g_esrc[N_EDGES];   // CSR-permuted src
__device__ float g_enorm[N_EDGES];  // CSR-permuted norm
__device__ float g_h1[N_NODES * C_HID];
__device__ float g_r [N_NODES * C_HID];
__device__ float g_h2[N_NODES * C_OUT];

// ---------------- 1. init ---------------------------------------------------
__global__ void k_init() {
    int i = blockIdx.x * blockDim.x + threadIdx.x;
    if (i < N_NODES) { g_deg[i] = 1.0f; g_cnt[i] = 0; g_fill[i] = 0; }
}

// ---------------- 2. narrow indices + degree histogram ----------------------
// edge_index is int32 on device (JAX x64 disabled -> int64 request silently
// becomes int32). Layout: [2, N_EDGES] row-major: src = ei[e], dst = ei[N_EDGES+e].
__global__ void k_pre(const int* __restrict__ ei,
                      const float* __restrict__ ew) {
    int e = blockIdx.x * blockDim.x + threadIdx.x;
    if (e >= N_EDGES) return;
    int s = ei[e];
    int d = ei[N_EDGES + e];
    g_src[e] = s;
    g_dst[e] = d;
    atomicAdd(&g_cnt[d], 1);
    atomicAdd(&g_deg[d], ew[e]);
}

// ---------------- 3. dinv ---------------------------------------------------
__global__ void k_dinv() {
    int i = blockIdx.x * blockDim.x + threadIdx.x;
    if (i < N_NODES) g_dinv[i] = rsqrtf(g_deg[i]);   // deg >= 1 (self loop)
}

// ---------------- 4. exclusive scan of cnt -> row ---------------------------
__global__ void k_scan1() {
    __shared__ int sm[SCAN_B];
    int gid = blockIdx.x * SCAN_B + threadIdx.x;
    int v = (gid < N_NODES) ? g_cnt[gid] : 0;
    sm[threadIdx.x] = v;
    __syncthreads();
#pragma unroll
    for (int off = 1; off < SCAN_B; off <<= 1) {
        int t = (threadIdx.x >= off) ? sm[threadIdx.x - off] : 0;
        __syncthreads();
        sm[threadIdx.x] += t;
        __syncthreads();
    }
    int incl = sm[threadIdx.x];
    if (gid < N_NODES) g_row[gid] = incl - v;
    if (threadIdx.x == SCAN_B - 1) g_bsum[blockIdx.x] = incl;
}

__global__ void k_scan2() {
    __shared__ int sm[512];
    int v = (threadIdx.x < N_SCAN_BLOCKS) ? g_bsum[threadIdx.x] : 0;
    sm[threadIdx.x] = v;
    __syncthreads();
#pragma unroll
    for (int off = 1; off < 512; off <<= 1) {
        int t = (threadIdx.x >= off) ? sm[threadIdx.x - off] : 0;
        __syncthreads();
        sm[threadIdx.x] += t;
        __syncthreads();
    }
    g_boff[threadIdx.x] = sm[threadIdx.x] - v;   // exclusive
}

__global__ void k_scan3() {
    int gid = blockIdx.x * SCAN_B + threadIdx.x;
    if (gid < N_NODES) g_row[gid] += g_boff[blockIdx.x];
}

// ---------------- 5. scatter edges into CSR buckets + norm ------------------
__global__ void k_scatter(const float* __restrict__ ew) {
    int e = blockIdx.x * blockDim.x + threadIdx.x;
    if (e >= N_EDGES) return;
    int s = g_src[e];
    int d = g_dst[e];
    int pos = g_row[d] + atomicAdd(&g_fill[d], 1);
    g_esrc[pos] = s;
    g_enorm[pos] = g_dinv[s] * ew[e] * g_dinv[d];
}

// ---------------- 6. GEMM1: h1 = x @ W1 -------------------------------------
__global__ void __launch_bounds__(128) k_gemm1(const float* __restrict__ x,
                                               const float* __restrict__ W1) {
    __shared__ float Ws[C_IN * C_HID];
    for (int i = threadIdx.x; i < C_IN * C_HID; i += blockDim.x) Ws[i] = W1[i];
    __syncthreads();
    int n = blockIdx.x * blockDim.x + threadIdx.x;
    if (n >= N_NODES) return;

    float acc[C_HID];
#pragma unroll
    for (int j = 0; j < C_HID; j++) acc[j] = 0.0f;

    const float4* xr = (const float4*)(x + (size_t)n * C_IN);
#pragma unroll 1
    for (int kk = 0; kk < C_IN / 4; kk++) {
        float4 xq = __ldg(xr + kk);
        float xv[4] = {xq.x, xq.y, xq.z, xq.w};
#pragma unroll
        for (int u = 0; u < 4; u++) {
            const float* wrow = Ws + (kk * 4 + u) * C_HID;
#pragma unroll
            for (int j = 0; j < C_HID; j++)
                acc[j] = fmaf(xv[u], wrow[j], acc[j]);
        }
    }
    float4* h1o = (float4*)(g_h1 + (size_t)n * C_HID);
#pragma unroll
    for (int q = 0; q < C_HID / 4; q++)
        h1o[q] = make_float4(acc[4*q], acc[4*q+1], acc[4*q+2], acc[4*q+3]);
}

// ---------------- 7. agg1 (warp/node): r = relu(A_hat @ h1 + b1) ------------
__global__ void __launch_bounds__(256) k_agg1(const float* __restrict__ b1) {
    int t = blockIdx.x * 256 + threadIdx.x;
    int n = t >> 5;
    int lane = t & 31;
    if (n >= N_NODES) return;

    int row = g_row[n];
    int cnt = g_cnt[n];
    float a0 = 0.0f, a1 = 0.0f;

    for (int base = 0; base < cnt; base += 32) {
        int k = base + lane;
        int s = 0; float w = 0.0f;
        if (k < cnt) { s = g_esrc[row + k]; w = g_enorm[row + k]; }
        int m = min(32, cnt - base);
        for (int j = 0; j < m; j++) {
            int   ss = __shfl_sync(0xffffffffu, s, j);
            float ww = __shfl_sync(0xffffffffu, w, j);
            const float* hp = g_h1 + ((size_t)ss << 6);
            a0 = fmaf(ww, hp[lane],      a0);
            a1 = fmaf(ww, hp[lane + 32], a1);
        }
    }
    float dv = g_dinv[n];
    float dv2 = dv * dv;
    const float* hn = g_h1 + ((size_t)n << 6);
    a0 = fmaf(dv2, hn[lane],      a0);
    a1 = fmaf(dv2, hn[lane + 32], a1);
    a0 = fmaxf(a0 + b1[lane],      0.0f);
    a1 = fmaxf(a1 + b1[lane + 32], 0.0f);
    float* rp = g_r + ((size_t)n << 6);
    rp[lane]      = a0;
    rp[lane + 32] = a1;
}

// ---------------- 8. GEMM2: h2 = r @ W2 -------------------------------------
__global__ void __launch_bounds__(128) k_gemm2(const float* __restrict__ W2) {
    __shared__ float Ws[C_HID * C_OUT];
    for (int i = threadIdx.x; i < C_HID * C_OUT; i += blockDim.x) Ws[i] = W2[i];
    __syncthreads();
    int n = blockIdx.x * blockDim.x + threadIdx.x;
    if (n >= N_NODES) return;

    float acc[C_OUT];
#pragma unroll
    for (int j = 0; j < C_OUT; j++) acc[j] = 0.0f;

    const float4* ar = (const float4*)(g_r + (size_t)n * C_HID);
#pragma unroll 1
    for (int kk = 0; kk < C_HID / 4; kk++) {
        float4 aq = ar[kk];
        float rv[4] = {aq.x, aq.y, aq.z, aq.w};
#pragma unroll
        for (int u = 0; u < 4; u++) {
            const float* wrow = Ws + (kk * 4 + u) * C_OUT;
#pragma unroll
            for (int j = 0; j < C_OUT; j++)
                acc[j] = fmaf(rv[u], wrow[j], acc[j]);
        }
    }
    float4* h2o = (float4*)(g_h2 + (size_t)n * C_OUT);
#pragma unroll
    for (int q = 0; q < C_OUT / 4; q++)
        h2o[q] = make_float4(acc[4*q], acc[4*q+1], acc[4*q+2], acc[4*q+3]);
}

// ---------------- 9. agg2 (warp/node): out = A_hat @ h2 + b2 ----------------
__global__ void __launch_bounds__(256) k_agg2(const float* __restrict__ b2,
                                              float* __restrict__ out) {
    int t = blockIdx.x * 256 + threadIdx.x;
    int n = t >> 5;
    int lane = t & 31;
    if (n >= N_NODES) return;

    int row = g_row[n];
    int cnt = g_cnt[n];
    float a = 0.0f;

    for (int base = 0; base < cnt; base += 32) {
        int k = base + lane;
        int s = 0; float w = 0.0f;
        if (k < cnt) { s = g_esrc[row + k]; w = g_enorm[row + k]; }
        int m = min(32, cnt - base);
        for (int j = 0; j < m; j++) {
            int   ss = __shfl_sync(0xffffffffu, s, j);
            float ww = __shfl_sync(0xffffffffu, w, j);
            a = fmaf(ww, g_h2[((size_t)ss << 5) + lane], a);
        }
    }
    float dv = g_dinv[n];
    a = fmaf(dv * dv, g_h2[((size_t)n << 5) + lane], a);
    out[((size_t)n << 5) + lane] = a + b2[lane];
}

// ---------------- launch ----------------------------------------------------
extern "C" void kernel_launch(void* const* d_in, const int* in_sizes, int n_in,
                              void* d_out, int out_size) {
    const float* x  = (const float*)d_in[0];
    const int*   ei = (const int*)d_in[1];     // int32 (JAX x64 disabled)
    const float* ew = (const float*)d_in[2];
    const float* W1 = (const float*)d_in[3];
    const float* b1 = (const float*)d_in[4];
    const float* W2 = (const float*)d_in[5];
    const float* b2 = (const float*)d_in[6];
    float* out = (float*)d_out;

    const int TB = 256;
    k_init   <<<(N_NODES + TB - 1) / TB, TB>>>();
    k_pre    <<<(N_EDGES + TB - 1) / TB, TB>>>(ei, ew);
    k_dinv   <<<(N_NODES + TB - 1) / TB, TB>>>();
    k_scan1  <<<N_SCAN_BLOCKS, SCAN_B>>>();
    k_scan2  <<<1, 512>>>();
    k_scan3  <<<N_SCAN_BLOCKS, SCAN_B>>>();
    k_scatter<<<(N_EDGES + TB - 1) / TB, TB>>>(ew);
    k_gemm1  <<<(N_NODES + 127) / 128, 128>>>(x, W1);
    k_agg1   <<<(N_NODES * 32) / 256, 256>>>(b1);
    k_gemm2  <<<(N_NODES + 127) / 128, 128>>>(W2);
    k_agg2   <<<(N_NODES * 32) / 256, 256>>>(b2, out);
}